// round 15
// baseline (speedup 1.0000x reference)
#include <cuda_runtime.h>
#include <cuda_bf16.h>
#include <math.h>
#include <float.h>
#include <stdint.h>

// ---------------- problem constants ----------------
constexpr int SEQ   = 2048;
constexpr int HIDN  = 2048;
constexpr int NHEAD = 16;
constexpr int NKVH  = 8;
constexpr int HDIM  = 128;
constexpr int QKVN  = (NHEAD + 2 * NKVH) * HDIM;   // 4096
constexpr float EPSF  = 1e-6f;
constexpr float SCALE = 0.08838834764831845f;      // 128^-0.5

// ---------------- scratch (static device, no allocs) ----------------
__device__ float g_hn    [(size_t)SEQ * HIDN];            // 16 MB
__device__ float g_qkv   [(size_t)SEQ * QKVN];            // 32 MB
__device__ float g_scores[(size_t)NHEAD * SEQ * SEQ];     // 256 MB
__device__ float g_attn  [(size_t)SEQ * NHEAD * HDIM];    // 16 MB
__device__ float g_vt    [(size_t)NKVH * HDIM * SEQ];     // 8 MB  (V transposed: [h][d][s])
__device__ float g_cos   [(size_t)SEQ * (HDIM / 2)];
__device__ float g_sin   [(size_t)SEQ * (HDIM / 2)];

#define SMEM_SWIZZLE_128B(off) ((off) ^ (((off) >> 3) & 0x70))

__device__ __forceinline__ uint32_t smem_u32(const void* p) {
    uint32_t a;
    asm("{ .reg .u64 t; cvta.to.shared.u64 t, %1; cvt.u32.u64 %0, t; }"
        : "=r"(a) : "l"(p));
    return a;
}

__device__ __forceinline__ void ldmatrix_x4(uint32_t* r, uint32_t addr) {
    asm volatile("ldmatrix.sync.aligned.m8n8.x4.shared.b16 {%0,%1,%2,%3}, [%4];"
        : "=r"(r[0]), "=r"(r[1]), "=r"(r[2]), "=r"(r[3]) : "r"(addr));
}

__device__ __forceinline__ void mma_f16(float* c, const uint32_t* a, const uint32_t* b) {
    asm volatile(
        "mma.sync.aligned.m16n8k16.row.col.f32.f16.f16.f32 "
        "{%0,%1,%2,%3}, {%4,%5,%6,%7}, {%8,%9}, {%0,%1,%2,%3};"
        : "+f"(c[0]), "+f"(c[1]), "+f"(c[2]), "+f"(c[3])
        : "r"(a[0]), "r"(a[1]), "r"(a[2]), "r"(a[3]), "r"(b[0]), "r"(b[1]));
}

// fp32x2 -> fp16x2 hi + fp16x2 lo split (x in low half, y in high half)
__device__ __forceinline__ void cvt_split2_f16(float x, float y, uint32_t& hi, uint32_t& lo)
{
    uint32_t h;
    asm("cvt.rn.f16x2.f32 %0, %1, %2;" : "=r"(h) : "f"(y), "f"(x));
    float hx, hy;
    asm("{.reg .f16 l, u; mov.b32 {l, u}, %2; cvt.f32.f16 %0, l; cvt.f32.f16 %1, u;}"
        : "=f"(hx), "=f"(hy) : "r"(h));
    float lx = x - hx;
    float ly = y - hy;
    uint32_t l;
    asm("cvt.rn.f16x2.f32 %0, %1, %2;" : "=r"(l) : "f"(ly), "f"(lx));
    hi = h;
    lo = l;
}
// fp32x2 -> fp16x2 single rounding
__device__ __forceinline__ uint32_t cvt2_f16(float x, float y)
{
    uint32_t h;
    asm("cvt.rn.f16x2.f32 %0, %1, %2;" : "=r"(h) : "f"(y), "f"(x));
    return h;
}

// ---------------- reductions ----------------
__device__ __forceinline__ float warp_sum(float v) {
    #pragma unroll
    for (int o = 16; o; o >>= 1) v += __shfl_xor_sync(0xffffffffu, v, o);
    return v;
}
__device__ __forceinline__ float warp_max(float v) {
    #pragma unroll
    for (int o = 16; o; o >>= 1) v = fmaxf(v, __shfl_xor_sync(0xffffffffu, v, o));
    return v;
}
template <int NT>
__device__ __forceinline__ float block_sum(float v) {
    __shared__ float sh[NT / 32];
    __syncthreads();
    v = warp_sum(v);
    int lane = threadIdx.x & 31, w = threadIdx.x >> 5;
    if (lane == 0) sh[w] = v;
    __syncthreads();
    if (w == 0) {
        float x = (lane < NT / 32) ? sh[lane] : 0.f;
        x = warp_sum(x);
        if (lane == 0) sh[0] = x;
    }
    __syncthreads();
    return sh[0];
}
template <int NT>
__device__ __forceinline__ float block_max(float v) {
    __shared__ float sh[NT / 32];
    __syncthreads();
    v = warp_max(v);
    int lane = threadIdx.x & 31, w = threadIdx.x >> 5;
    if (lane == 0) sh[w] = v;
    __syncthreads();
    if (w == 0) {
        float x = (lane < NT / 32) ? sh[lane] : -FLT_MAX;
        x = warp_max(x);
        if (lane == 0) sh[0] = x;
    }
    __syncthreads();
    return sh[0];
}

// ---------------- 1. RMSNorm(hidden) ----------------
__global__ void __launch_bounds__(256) k_rmsnorm_hidden(
    const float* __restrict__ x, const float* __restrict__ w)
{
    int row = blockIdx.x;
    const float* xr = x    + (size_t)row * HIDN;
    float*       yr = g_hn + (size_t)row * HIDN;
    float ss = 0.f;
    for (int i = threadIdx.x; i < HIDN; i += 256) { float v = xr[i]; ss = fmaf(v, v, ss); }
    ss = block_sum<256>(ss);
    float r = rsqrtf(ss * (1.f / HIDN) + EPSF);
    for (int i = threadIdx.x; i < HIDN; i += 256) yr[i] = xr[i] * r * w[i];
}

// ---------------- 2. RoPE cos/sin table ----------------
__global__ void k_rope_table(const int* __restrict__ positions)
{
    int idx = blockIdx.x * blockDim.x + threadIdx.x;
    if (idx >= SEQ * (HDIM / 2)) return;
    int s = idx / (HDIM / 2);
    int d = idx % (HDIM / 2);
    double inv = exp(-(double)d * (log(10000.0) / 64.0));
    double ph  = (double)positions[s] * inv;
    double sd, cd;
    sincos(ph, &sd, &cd);
    g_cos[idx] = (float)cd;
    g_sin[idx] = (float)sd;
}

// =====================================================================
// Tensor-core fp16 asymmetric-split GEMM, NT, double-buffered smem with
// register-staged prefetch and convert/STS interleaved into the MMA
// stream (slice kc of the staged registers is converted between the
// kc-th MMA block and the next ldmatrix block — dual-issues vs HMMA):
//   C = alpha * A @ B^T;  A split to fp16 hi+lo, B rounded to fp16 once.
//   acc += a_hi*b ; acc += a_lo*b     (2 MMAs; dropped term ~2^-12)
// CTA tile M=128, N=128, BK=64 fp32. 256 threads = 8 warps in 4x2,
// warp tile 32x64, mma.sync m16n8k16 + ldmatrix from SW128-swizzled smem.
// K must be a multiple of 64.
// =====================================================================
constexpr int STAGE_BYTES = 3 * 16384;               // Ahi|Alo|B per stage
constexpr int GEMM_DSMEM  = 2 * STAGE_BYTES + 128;

__device__ void tc_gemm_nt(const float* __restrict__ A, const float* __restrict__ B,
                           float* __restrict__ C, int lda, int ldb, int ldc,
                           int K, float alpha, int bm, int bn)
{
    extern __shared__ char dynsmem[];
    char* sm = (char*)(((uintptr_t)dynsmem + 127) & ~(uintptr_t)127);
    uint32_t base = smem_u32(sm);

    int tid = threadIdx.x, wid = tid >> 5, lane = tid & 31;
    int wr = wid >> 1, wc = wid & 1;        // warp grid 4 x 2

    float acc[2][8][4];
    #pragma unroll
    for (int mt = 0; mt < 2; mt++)
        #pragma unroll
        for (int nt = 0; nt < 8; nt++)
            #pragma unroll
            for (int j = 0; j < 4; j++) acc[mt][nt][j] = 0.f;

    // loader: thread owns k-pair (2*lane); warp wid handles rows wid, wid+8, ...
    const float* Ab = A + (size_t)bm * lda + 2 * lane;
    const float* Bb = B + (size_t)bn * ldb + 2 * lane;

    // ldmatrix lane geometry (byte offsets pre-swizzle) — verified R8/R12/R13
    int a_row = wr * 32 + (lane & 7) + (((lane >> 3) & 1) << 3);   // + mt*16
    int a_kb  = ((lane >> 4) & 1) << 4;                            // + kc*32
    int b_row = wc * 64 + (lane & 7) + (((lane >> 4) & 1) << 3);   // + np*16
    int b_kb  = ((lane >> 3) & 1) << 4;

    int nch = K >> 6;

    // ---- fill stage 0 directly (chunk 0) ----
    {
        char* tAhi = sm;
        char* tAlo = sm + 16384;
        char* tB   = sm + 32768;
        #pragma unroll 4
        for (int r = wid; r < 128; r += 8) {
            uint32_t off = SMEM_SWIZZLE_128B((uint32_t)(r * 128 + lane * 4));
            float2 va = *(const float2*)(Ab + (size_t)r * lda);
            uint32_t h, l;
            cvt_split2_f16(va.x, va.y, h, l);
            *(uint32_t*)(tAhi + off) = h;
            *(uint32_t*)(tAlo + off) = l;
            float2 vb = *(const float2*)(Bb + (size_t)r * ldb);
            *(uint32_t*)(tB + off) = cvt2_f16(vb.x, vb.y);
        }
    }
    __syncthreads();

    for (int c = 0; c < nch; c++) {
        // ---- 1. prefetch next chunk's data into registers (LDG only) ----
        float2 stA[16], stB[16];
        bool pf = (c + 1 < nch);
        if (pf) {
            int k1 = (c + 1) << 6;
            #pragma unroll
            for (int j = 0; j < 16; j++) {
                int r = wid + 8 * j;
                stA[j] = *(const float2*)(Ab + (size_t)r * lda + k1);
                stB[j] = *(const float2*)(Bb + (size_t)r * ldb + k1);
            }
        }

        // ---- 2. MMAs on stage (c&1), with convert/STS of staged regs
        //         into the other stage interleaved per kc slice ----
        uint32_t sb = base + (c & 1) * STAGE_BYTES;
        uint32_t aAhi = sb, aAlo = sb + 16384, aB = sb + 32768;
        char* nAhi = sm + ((c + 1) & 1) * STAGE_BYTES;
        char* nAlo = nAhi + 16384;
        char* nB   = nAhi + 32768;

        #pragma unroll
        for (int kc = 0; kc < 4; kc++) {
            uint32_t ahi[2][4], alo[2][4], bfr[4][4];
            #pragma unroll
            for (int mt = 0; mt < 2; mt++) {
                uint32_t off = SMEM_SWIZZLE_128B(
                    (uint32_t)((a_row + mt * 16) * 128 + kc * 32 + a_kb));
                ldmatrix_x4(ahi[mt], aAhi + off);
                ldmatrix_x4(alo[mt], aAlo + off);
            }
            #pragma unroll
            for (int np = 0; np < 4; np++) {
                uint32_t off = SMEM_SWIZZLE_128B(
                    (uint32_t)((b_row + np * 16) * 128 + kc * 32 + b_kb));
                ldmatrix_x4(bfr[np], aB + off);
            }
            #pragma unroll
            for (int mt = 0; mt < 2; mt++)
                #pragma unroll
                for (int nt = 0; nt < 8; nt++) {
                    const uint32_t* bh = &bfr[nt >> 1][(nt & 1) * 2];
                    mma_f16(acc[mt][nt], ahi[mt], bh);   // a_hi * b
                    mma_f16(acc[mt][nt], alo[mt], bh);   // a_lo * b
                }
            // convert + store slice kc of the staged registers (other stage,
            // no hazard with the ldmatrix reads above; dual-issues vs HMMA)
            if (pf) {
                #pragma unroll
                for (int j = kc * 4; j < kc * 4 + 4; j++) {
                    int r = wid + 8 * j;
                    uint32_t off = SMEM_SWIZZLE_128B((uint32_t)(r * 128 + lane * 4));
                    uint32_t h, l;
                    cvt_split2_f16(stA[j].x, stA[j].y, h, l);
                    *(uint32_t*)(nAhi + off) = h;
                    *(uint32_t*)(nAlo + off) = l;
                    *(uint32_t*)(nB + off) = cvt2_f16(stB[j].x, stB[j].y);
                }
            }
        }
        __syncthreads();
    }

    // epilogue: c0,c1 at (m = lane/4, n = 2*(lane%4)); c2,c3 at m+8
    int row0 = bm + wr * 32 + (lane >> 2);
    int col0 = bn + wc * 64 + (lane & 3) * 2;
    #pragma unroll
    for (int mt = 0; mt < 2; mt++)
        #pragma unroll
        for (int nt = 0; nt < 8; nt++) {
            float* c0 = C + (size_t)(row0 + mt * 16)     * ldc + col0 + nt * 8;
            float* c1 = C + (size_t)(row0 + mt * 16 + 8) * ldc + col0 + nt * 8;
            *(float2*)c0 = make_float2(alpha * acc[mt][nt][0], alpha * acc[mt][nt][1]);
            *(float2*)c1 = make_float2(alpha * acc[mt][nt][2], alpha * acc[mt][nt][3]);
        }
}

// ---------------- GEMM wrappers ----------------
__global__ void __launch_bounds__(256, 1) k_tc_qkv(const float* __restrict__ w_qkv)
{
    tc_gemm_nt(g_hn, w_qkv, g_qkv, HIDN, HIDN, QKVN, HIDN, 1.f,
               blockIdx.y * 128, blockIdx.x * 128);
}

__global__ void __launch_bounds__(256, 1) k_tc_scores()
{
    if (blockIdx.x > blockIdx.y) return;   // fully above diagonal: never read
    int h = blockIdx.z;
    tc_gemm_nt(g_qkv + (size_t)h * HDIM,
               g_qkv + (size_t)NHEAD * HDIM + (size_t)(h >> 1) * HDIM,
               g_scores + (size_t)h * SEQ * SEQ,
               QKVN, QKVN, SEQ, HDIM, SCALE,
               blockIdx.y * 128, blockIdx.x * 128);
}

__global__ void __launch_bounds__(256, 1) k_tc_pv()
{
    int h = blockIdx.z, bm = blockIdx.y * 128;
    tc_gemm_nt(g_scores + (size_t)h * SEQ * SEQ,
               g_vt + (size_t)(h >> 1) * HDIM * SEQ,
               g_attn + (size_t)h * HDIM,
               SEQ, SEQ, NHEAD * HDIM, bm + 128 /* causal K truncation */, 1.f,
               bm, 0);
}

__global__ void __launch_bounds__(256, 1) k_tc_oproj(
    const float* __restrict__ w_o, float* __restrict__ out)
{
    tc_gemm_nt(g_attn, w_o, out, NHEAD * HDIM, NHEAD * HDIM, HIDN,
               NHEAD * HDIM, 1.f, blockIdx.y * 128, blockIdx.x * 128);
}

// ---------------- per-head q/k RMSNorm + RoPE (warp-per-head, in place) ----------------
__global__ void __launch_bounds__(256) k_qknorm_rope(
    const float* __restrict__ qw, const float* __restrict__ kw)
{
    int s    = blockIdx.x;
    int wid  = threadIdx.x >> 5, lane = threadIdx.x & 31;
    float c0 = g_cos[(size_t)s * 64 + lane];
    float s0 = g_sin[(size_t)s * 64 + lane];
    float c1 = g_cos[(size_t)s * 64 + lane + 32];
    float s1 = g_sin[(size_t)s * 64 + lane + 32];

    for (int hidx = wid; hidx < NHEAD + NKVH; hidx += 8) {
        float* x;
        const float* w;
        if (hidx < NHEAD) { x = g_qkv + (size_t)s * QKVN + (size_t)hidx * HDIM; w = qw; }
        else              { x = g_qkv + (size_t)s * QKVN + (size_t)NHEAD * HDIM
                                  + (size_t)(hidx - NHEAD) * HDIM;              w = kw; }
        float v0 = x[lane], v1 = x[lane + 32], v2 = x[lane + 64], v3 = x[lane + 96];
        float ss = warp_sum(v0 * v0 + v1 * v1 + v2 * v2 + v3 * v3);
        float r  = rsqrtf(ss * (1.f / HDIM) + EPSF);
        float n0 = v0 * r * w[lane];
        float n1 = v1 * r * w[lane + 32];
        float n2 = v2 * r * w[lane + 64];
        float n3 = v3 * r * w[lane + 96];
        x[lane]      = n0 * c0 - n2 * s0;
        x[lane + 64] = n2 * c0 + n0 * s0;
        x[lane + 32] = n1 * c1 - n3 * s1;
        x[lane + 96] = n3 * c1 + n1 * s1;
    }
}

// ---------------- V transpose: g_vt[h][d][s] = V[s][h][d] ----------------
__global__ void k_transpose_v()
{
    __shared__ float t[32][33];
    int h  = blockIdx.z;
    int s0 = blockIdx.x * 32, d0 = blockIdx.y * 32;
    const float* src = g_qkv + (size_t)(NHEAD + NKVH) * HDIM + (size_t)h * HDIM;
    for (int i = threadIdx.y; i < 32; i += 8)
        t[i][threadIdx.x] = src[(size_t)(s0 + i) * QKVN + d0 + threadIdx.x];
    __syncthreads();
    float* dst = g_vt + (size_t)h * HDIM * SEQ;
    for (int i = threadIdx.y; i < 32; i += 8)
        dst[(size_t)(d0 + i) * SEQ + s0 + threadIdx.x] = t[threadIdx.x][i];
}

// ---------------- causal softmax (writes only cols < diag-block end) ----------------
__global__ void __launch_bounds__(256) k_softmax()
{
    int row = blockIdx.x, h = blockIdx.y;
    float* p = g_scores + (size_t)h * SEQ * SEQ + (size_t)row * SEQ;
    int n   = row + 1;
    int lim = (row & ~127) + 128;          // PV only reads cols < lim for this row
    int tid = threadIdx.x;
    float loc[8];
    float m = -FLT_MAX;
    #pragma unroll
    for (int j = 0; j < 8; j++) {
        int i = tid + j * 256;
        float v = (i < n) ? p[i] : -FLT_MAX;
        loc[j] = v;
        m = fmaxf(m, v);
    }
    m = block_max<256>(m);
    float sum = 0.f;
    #pragma unroll
    for (int j = 0; j < 8; j++) {
        int i = tid + j * 256;
        float e = (i < n) ? __expf(loc[j] - m) : 0.f;
        loc[j] = e;
        sum += e;
    }
    sum = block_sum<256>(sum);
    float rinv = 1.f / sum;
    #pragma unroll
    for (int j = 0; j < 8; j++) {
        int i = tid + j * 256;
        if (i < lim) p[i] = loc[j] * rinv;   // zeros above diag within block
    }
}

// ---------------- launch ----------------
extern "C" void kernel_launch(void* const* d_in, const int* in_sizes, int n_in,
                              void* d_out, int out_size)
{
    const int*   positions = (const int*)  d_in[0];
    const float* hidden    = (const float*)d_in[1];
    const float* ln_w      = (const float*)d_in[2];
    const float* w_qkv     = (const float*)d_in[3];
    const float* w_o       = (const float*)d_in[4];
    const float* q_norm_w  = (const float*)d_in[5];
    const float* k_norm_w  = (const float*)d_in[6];
    float*       out       = (float*)d_out;

    // opt in to >48KB dynamic smem (idempotent; not a stream op)
    cudaFuncSetAttribute(k_tc_qkv,    cudaFuncAttributeMaxDynamicSharedMemorySize, GEMM_DSMEM);
    cudaFuncSetAttribute(k_tc_scores, cudaFuncAttributeMaxDynamicSharedMemorySize, GEMM_DSMEM);
    cudaFuncSetAttribute(k_tc_pv,     cudaFuncAttributeMaxDynamicSharedMemorySize, GEMM_DSMEM);
    cudaFuncSetAttribute(k_tc_oproj,  cudaFuncAttributeMaxDynamicSharedMemorySize, GEMM_DSMEM);

    k_rmsnorm_hidden<<<SEQ, 256>>>(hidden, ln_w);
    k_rope_table<<<(SEQ * (HDIM / 2) + 255) / 256, 256>>>(positions);
    k_tc_qkv<<<dim3(QKVN / 128, SEQ / 128), 256, GEMM_DSMEM>>>(w_qkv);
    k_qknorm_rope<<<SEQ, 256>>>(q_norm_w, k_norm_w);
    k_transpose_v<<<dim3(SEQ / 32, HDIM / 32, NKVH), dim3(32, 8)>>>();
    k_tc_scores<<<dim3(SEQ / 128, SEQ / 128, NHEAD), 256, GEMM_DSMEM>>>();
    k_softmax<<<dim3(SEQ, NHEAD), 256>>>();
    k_tc_pv<<<dim3(1, SEQ / 128, NHEAD), 256, GEMM_DSMEM>>>();
    k_tc_oproj<<<dim3(HIDN / 128, SEQ / 128), 256, GEMM_DSMEM>>>(w_o, out);
}

// round 16
// speedup vs baseline: 1.1003x; 1.1003x over previous
#include <cuda_runtime.h>
#include <cuda_bf16.h>
#include <math.h>
#include <float.h>
#include <stdint.h>

// ---------------- problem constants ----------------
constexpr int SEQ   = 2048;
constexpr int HIDN  = 2048;
constexpr int NHEAD = 16;
constexpr int NKVH  = 8;
constexpr int HDIM  = 128;
constexpr int QKVN  = (NHEAD + 2 * NKVH) * HDIM;   // 4096
constexpr float EPSF  = 1e-6f;
constexpr float SCALE = 0.08838834764831845f;      // 128^-0.5

// ---------------- scratch (static device, no allocs) ----------------
__device__ float g_hn    [(size_t)SEQ * HIDN];            // 16 MB
__device__ float g_qkv   [(size_t)SEQ * QKVN];            // 32 MB
__device__ float g_scores[(size_t)NHEAD * SEQ * SEQ];     // 256 MB
__device__ float g_attn  [(size_t)SEQ * NHEAD * HDIM];    // 16 MB
__device__ float g_vt    [(size_t)NKVH * HDIM * SEQ];     // 8 MB  (V transposed: [h][d][s])
__device__ float g_cos   [(size_t)SEQ * (HDIM / 2)];
__device__ float g_sin   [(size_t)SEQ * (HDIM / 2)];

#define SMEM_SWIZZLE_128B(off) ((off) ^ (((off) >> 3) & 0x70))

__device__ __forceinline__ uint32_t smem_u32(const void* p) {
    uint32_t a;
    asm("{ .reg .u64 t; cvta.to.shared.u64 t, %1; cvt.u32.u64 %0, t; }"
        : "=r"(a) : "l"(p));
    return a;
}

__device__ __forceinline__ void ldmatrix_x4(uint32_t* r, uint32_t addr) {
    asm volatile("ldmatrix.sync.aligned.m8n8.x4.shared.b16 {%0,%1,%2,%3}, [%4];"
        : "=r"(r[0]), "=r"(r[1]), "=r"(r[2]), "=r"(r[3]) : "r"(addr));
}

__device__ __forceinline__ void mma_f16(float* c, const uint32_t* a, const uint32_t* b) {
    asm volatile(
        "mma.sync.aligned.m16n8k16.row.col.f32.f16.f16.f32 "
        "{%0,%1,%2,%3}, {%4,%5,%6,%7}, {%8,%9}, {%0,%1,%2,%3};"
        : "+f"(c[0]), "+f"(c[1]), "+f"(c[2]), "+f"(c[3])
        : "r"(a[0]), "r"(a[1]), "r"(a[2]), "r"(a[3]), "r"(b[0]), "r"(b[1]));
}

// fp32x2 -> fp16x2 hi + fp16x2 lo split (x in low half, y in high half)
__device__ __forceinline__ void cvt_split2_f16(float x, float y, uint32_t& hi, uint32_t& lo)
{
    uint32_t h;
    asm("cvt.rn.f16x2.f32 %0, %1, %2;" : "=r"(h) : "f"(y), "f"(x));
    float hx, hy;
    asm("{.reg .f16 l, u; mov.b32 {l, u}, %2; cvt.f32.f16 %0, l; cvt.f32.f16 %1, u;}"
        : "=f"(hx), "=f"(hy) : "r"(h));
    float lx = x - hx;
    float ly = y - hy;
    uint32_t l;
    asm("cvt.rn.f16x2.f32 %0, %1, %2;" : "=r"(l) : "f"(ly), "f"(lx));
    hi = h;
    lo = l;
}
// fp32x2 -> fp16x2 single rounding
__device__ __forceinline__ uint32_t cvt2_f16(float x, float y)
{
    uint32_t h;
    asm("cvt.rn.f16x2.f32 %0, %1, %2;" : "=r"(h) : "f"(y), "f"(x));
    return h;
}

// ---------------- reductions ----------------
__device__ __forceinline__ float warp_sum(float v) {
    #pragma unroll
    for (int o = 16; o; o >>= 1) v += __shfl_xor_sync(0xffffffffu, v, o);
    return v;
}
__device__ __forceinline__ float warp_max(float v) {
    #pragma unroll
    for (int o = 16; o; o >>= 1) v = fmaxf(v, __shfl_xor_sync(0xffffffffu, v, o));
    return v;
}
template <int NT>
__device__ __forceinline__ float block_sum(float v) {
    __shared__ float sh[NT / 32];
    __syncthreads();
    v = warp_sum(v);
    int lane = threadIdx.x & 31, w = threadIdx.x >> 5;
    if (lane == 0) sh[w] = v;
    __syncthreads();
    if (w == 0) {
        float x = (lane < NT / 32) ? sh[lane] : 0.f;
        x = warp_sum(x);
        if (lane == 0) sh[0] = x;
    }
    __syncthreads();
    return sh[0];
}
template <int NT>
__device__ __forceinline__ float block_max(float v) {
    __shared__ float sh[NT / 32];
    __syncthreads();
    v = warp_max(v);
    int lane = threadIdx.x & 31, w = threadIdx.x >> 5;
    if (lane == 0) sh[w] = v;
    __syncthreads();
    if (w == 0) {
        float x = (lane < NT / 32) ? sh[lane] : -FLT_MAX;
        x = warp_max(x);
        if (lane == 0) sh[0] = x;
    }
    __syncthreads();
    return sh[0];
}

// ---------------- 1. RMSNorm(hidden) ----------------
__global__ void __launch_bounds__(256) k_rmsnorm_hidden(
    const float* __restrict__ x, const float* __restrict__ w)
{
    int row = blockIdx.x;
    const float* xr = x    + (size_t)row * HIDN;
    float*       yr = g_hn + (size_t)row * HIDN;
    float ss = 0.f;
    for (int i = threadIdx.x; i < HIDN; i += 256) { float v = xr[i]; ss = fmaf(v, v, ss); }
    ss = block_sum<256>(ss);
    float r = rsqrtf(ss * (1.f / HIDN) + EPSF);
    for (int i = threadIdx.x; i < HIDN; i += 256) yr[i] = xr[i] * r * w[i];
}

// ---------------- 2. RoPE cos/sin table ----------------
__global__ void k_rope_table(const int* __restrict__ positions)
{
    int idx = blockIdx.x * blockDim.x + threadIdx.x;
    if (idx >= SEQ * (HDIM / 2)) return;
    int s = idx / (HDIM / 2);
    int d = idx % (HDIM / 2);
    double inv = exp(-(double)d * (log(10000.0) / 64.0));
    double ph  = (double)positions[s] * inv;
    double sd, cd;
    sincos(ph, &sd, &cd);
    g_cos[idx] = (float)cd;
    g_sin[idx] = (float)sd;
}

// =====================================================================
// Tensor-core fp16 asymmetric-split GEMM, NT, double-buffered smem with
// register-staged prefetch (R14 mainloop, verified 815us / 4.95e-4):
//   C = alpha * A @ B^T;  A split to fp16 hi+lo, B rounded to fp16 once.
//   acc += a_hi*b ; acc += a_lo*b     (2 MMAs; dropped term ~2^-12)
// CTA tile M=128, N=128, BK=64 fp32. 256 threads = 8 warps in 4x2,
// warp tile 32x64, mma.sync m16n8k16 + ldmatrix from SW128-swizzled smem.
// K must be a multiple of 64.
// =====================================================================
constexpr int STAGE_BYTES = 3 * 16384;               // Ahi|Alo|B per stage
constexpr int GEMM_DSMEM  = 2 * STAGE_BYTES + 128;

__device__ void tc_gemm_nt(const float* __restrict__ A, const float* __restrict__ B,
                           float* __restrict__ C, int lda, int ldb, int ldc,
                           int K, float alpha, int bm, int bn)
{
    extern __shared__ char dynsmem[];
    char* sm = (char*)(((uintptr_t)dynsmem + 127) & ~(uintptr_t)127);
    uint32_t base = smem_u32(sm);

    int tid = threadIdx.x, wid = tid >> 5, lane = tid & 31;
    int wr = wid >> 1, wc = wid & 1;        // warp grid 4 x 2

    float acc[2][8][4];
    #pragma unroll
    for (int mt = 0; mt < 2; mt++)
        #pragma unroll
        for (int nt = 0; nt < 8; nt++)
            #pragma unroll
            for (int j = 0; j < 4; j++) acc[mt][nt][j] = 0.f;

    // loader: thread owns k-pair (2*lane); warp wid handles rows wid, wid+8, ...
    const float* Ab = A + (size_t)bm * lda + 2 * lane;
    const float* Bb = B + (size_t)bn * ldb + 2 * lane;

    // ldmatrix lane geometry (byte offsets pre-swizzle) — verified R8/R12/R13
    int a_row = wr * 32 + (lane & 7) + (((lane >> 3) & 1) << 3);   // + mt*16
    int a_kb  = ((lane >> 4) & 1) << 4;                            // + kc*32
    int b_row = wc * 64 + (lane & 7) + (((lane >> 4) & 1) << 3);   // + np*16
    int b_kb  = ((lane >> 3) & 1) << 4;

    int nch = K >> 6;

    // ---- fill stage 0 directly (chunk 0) ----
    {
        char* tAhi = sm;
        char* tAlo = sm + 16384;
        char* tB   = sm + 32768;
        #pragma unroll 4
        for (int r = wid; r < 128; r += 8) {
            uint32_t off = SMEM_SWIZZLE_128B((uint32_t)(r * 128 + lane * 4));
            float2 va = *(const float2*)(Ab + (size_t)r * lda);
            uint32_t h, l;
            cvt_split2_f16(va.x, va.y, h, l);
            *(uint32_t*)(tAhi + off) = h;
            *(uint32_t*)(tAlo + off) = l;
            float2 vb = *(const float2*)(Bb + (size_t)r * ldb);
            *(uint32_t*)(tB + off) = cvt2_f16(vb.x, vb.y);
        }
    }
    __syncthreads();

    for (int c = 0; c < nch; c++) {
        // ---- 1. prefetch next chunk's data into registers (LDG only) ----
        float2 stA[16], stB[16];
        bool pf = (c + 1 < nch);
        if (pf) {
            int k1 = (c + 1) << 6;
            #pragma unroll
            for (int j = 0; j < 16; j++) {
                int r = wid + 8 * j;
                stA[j] = *(const float2*)(Ab + (size_t)r * lda + k1);
                stB[j] = *(const float2*)(Bb + (size_t)r * ldb + k1);
            }
        }

        // ---- 2. MMAs on stage (c&1) — covers the LDG latency ----
        uint32_t sb = base + (c & 1) * STAGE_BYTES;
        uint32_t aAhi = sb, aAlo = sb + 16384, aB = sb + 32768;

        #pragma unroll
        for (int kc = 0; kc < 4; kc++) {
            uint32_t ahi[2][4], alo[2][4], bfr[4][4];
            #pragma unroll
            for (int mt = 0; mt < 2; mt++) {
                uint32_t off = SMEM_SWIZZLE_128B(
                    (uint32_t)((a_row + mt * 16) * 128 + kc * 32 + a_kb));
                ldmatrix_x4(ahi[mt], aAhi + off);
                ldmatrix_x4(alo[mt], aAlo + off);
            }
            #pragma unroll
            for (int np = 0; np < 4; np++) {
                uint32_t off = SMEM_SWIZZLE_128B(
                    (uint32_t)((b_row + np * 16) * 128 + kc * 32 + b_kb));
                ldmatrix_x4(bfr[np], aB + off);
            }
            #pragma unroll
            for (int mt = 0; mt < 2; mt++)
                #pragma unroll
                for (int nt = 0; nt < 8; nt++) {
                    const uint32_t* bh = &bfr[nt >> 1][(nt & 1) * 2];
                    mma_f16(acc[mt][nt], ahi[mt], bh);   // a_hi * b
                    mma_f16(acc[mt][nt], alo[mt], bh);   // a_lo * b
                }
        }

        // ---- 3. convert + store staged registers into the other stage ----
        if (pf) {
            char* tAhi = sm + ((c + 1) & 1) * STAGE_BYTES;
            char* tAlo = tAhi + 16384;
            char* tB   = tAhi + 32768;
            #pragma unroll
            for (int j = 0; j < 16; j++) {
                int r = wid + 8 * j;
                uint32_t off = SMEM_SWIZZLE_128B((uint32_t)(r * 128 + lane * 4));
                uint32_t h, l;
                cvt_split2_f16(stA[j].x, stA[j].y, h, l);
                *(uint32_t*)(tAhi + off) = h;
                *(uint32_t*)(tAlo + off) = l;
                *(uint32_t*)(tB + off) = cvt2_f16(stB[j].x, stB[j].y);
            }
        }
        __syncthreads();
    }

    // epilogue: c0,c1 at (m = lane/4, n = 2*(lane%4)); c2,c3 at m+8
    int row0 = bm + wr * 32 + (lane >> 2);
    int col0 = bn + wc * 64 + (lane & 3) * 2;
    #pragma unroll
    for (int mt = 0; mt < 2; mt++)
        #pragma unroll
        for (int nt = 0; nt < 8; nt++) {
            float* c0 = C + (size_t)(row0 + mt * 16)     * ldc + col0 + nt * 8;
            float* c1 = C + (size_t)(row0 + mt * 16 + 8) * ldc + col0 + nt * 8;
            *(float2*)c0 = make_float2(alpha * acc[mt][nt][0], alpha * acc[mt][nt][1]);
            *(float2*)c1 = make_float2(alpha * acc[mt][nt][2], alpha * acc[mt][nt][3]);
        }
}

// ---------------- GEMM wrappers ----------------
__global__ void __launch_bounds__(256, 1) k_tc_qkv(const float* __restrict__ w_qkv)
{
    tc_gemm_nt(g_hn, w_qkv, g_qkv, HIDN, HIDN, QKVN, HIDN, 1.f,
               blockIdx.y * 128, blockIdx.x * 128);
}

// compacted triangular grid: 2176 CTAs, bid -> (head, by, bx), no dead CTAs
constexpr int TRI_TILES = (SEQ / 128) * (SEQ / 128 + 1) / 2;   // 136
__global__ void __launch_bounds__(256, 1) k_tc_scores()
{
    int t = blockIdx.x;                 // 0..135 triangular index
    int h = blockIdx.y;                 // head
    // by = largest b with b(b+1)/2 <= t
    int by = (int)((sqrtf(8.f * t + 1.f) - 1.f) * 0.5f);
    while ((by + 1) * (by + 2) / 2 <= t) by++;
    while (by * (by + 1) / 2 > t) by--;
    int bx = t - by * (by + 1) / 2;     // 0..by
    tc_gemm_nt(g_qkv + (size_t)h * HDIM,
               g_qkv + (size_t)NHEAD * HDIM + (size_t)(h >> 1) * HDIM,
               g_scores + (size_t)h * SEQ * SEQ,
               QKVN, QKVN, SEQ, HDIM, SCALE,
               by * 128, bx * 128);
}

// PV with LPT scheduling: heaviest row-blocks (largest bm -> most K chunks) first
__global__ void __launch_bounds__(256, 1) k_tc_pv()
{
    int bid = blockIdx.x;               // 0..255
    int rb  = (SEQ / 128 - 1) - (bid >> 4);   // 15,15,...,0 (heavy first)
    int h   = bid & 15;
    int bm  = rb * 128;
    tc_gemm_nt(g_scores + (size_t)h * SEQ * SEQ,
               g_vt + (size_t)(h >> 1) * HDIM * SEQ,
               g_attn + (size_t)h * HDIM,
               SEQ, SEQ, NHEAD * HDIM, bm + 128 /* causal K truncation */, 1.f,
               bm, 0);
}

__global__ void __launch_bounds__(256, 1) k_tc_oproj(
    const float* __restrict__ w_o, float* __restrict__ out)
{
    tc_gemm_nt(g_attn, w_o, out, NHEAD * HDIM, NHEAD * HDIM, HIDN,
               NHEAD * HDIM, 1.f, blockIdx.y * 128, blockIdx.x * 128);
}

// ---------------- per-head q/k RMSNorm + RoPE (warp-per-head, in place) ----------------
__global__ void __launch_bounds__(256) k_qknorm_rope(
    const float* __restrict__ qw, const float* __restrict__ kw)
{
    int s    = blockIdx.x;
    int wid  = threadIdx.x >> 5, lane = threadIdx.x & 31;
    float c0 = g_cos[(size_t)s * 64 + lane];
    float s0 = g_sin[(size_t)s * 64 + lane];
    float c1 = g_cos[(size_t)s * 64 + lane + 32];
    float s1 = g_sin[(size_t)s * 64 + lane + 32];

    for (int hidx = wid; hidx < NHEAD + NKVH; hidx += 8) {
        float* x;
        const float* w;
        if (hidx < NHEAD) { x = g_qkv + (size_t)s * QKVN + (size_t)hidx * HDIM; w = qw; }
        else              { x = g_qkv + (size_t)s * QKVN + (size_t)NHEAD * HDIM
                                  + (size_t)(hidx - NHEAD) * HDIM;              w = kw; }
        float v0 = x[lane], v1 = x[lane + 32], v2 = x[lane + 64], v3 = x[lane + 96];
        float ss = warp_sum(v0 * v0 + v1 * v1 + v2 * v2 + v3 * v3);
        float r  = rsqrtf(ss * (1.f / HDIM) + EPSF);
        float n0 = v0 * r * w[lane];
        float n1 = v1 * r * w[lane + 32];
        float n2 = v2 * r * w[lane + 64];
        float n3 = v3 * r * w[lane + 96];
        x[lane]      = n0 * c0 - n2 * s0;
        x[lane + 64] = n2 * c0 + n0 * s0;
        x[lane + 32] = n1 * c1 - n3 * s1;
        x[lane + 96] = n3 * c1 + n1 * s1;
    }
}

// ---------------- V transpose: g_vt[h][d][s] = V[s][h][d] ----------------
__global__ void k_transpose_v()
{
    __shared__ float t[32][33];
    int h  = blockIdx.z;
    int s0 = blockIdx.x * 32, d0 = blockIdx.y * 32;
    const float* src = g_qkv + (size_t)(NHEAD + NKVH) * HDIM + (size_t)h * HDIM;
    for (int i = threadIdx.y; i < 32; i += 8)
        t[i][threadIdx.x] = src[(size_t)(s0 + i) * QKVN + d0 + threadIdx.x];
    __syncthreads();
    float* dst = g_vt + (size_t)h * HDIM * SEQ;
    for (int i = threadIdx.y; i < 32; i += 8)
        dst[(size_t)(d0 + i) * SEQ + s0 + threadIdx.x] = t[threadIdx.x][i];
}

// ---------------- causal softmax (writes only cols < diag-block end) ----------------
__global__ void __launch_bounds__(256) k_softmax()
{
    int row = blockIdx.x, h = blockIdx.y;
    float* p = g_scores + (size_t)h * SEQ * SEQ + (size_t)row * SEQ;
    int n   = row + 1;
    int lim = (row & ~127) + 128;          // PV only reads cols < lim for this row
    int tid = threadIdx.x;
    float loc[8];
    float m = -FLT_MAX;
    #pragma unroll
    for (int j = 0; j < 8; j++) {
        int i = tid + j * 256;
        float v = (i < n) ? p[i] : -FLT_MAX;
        loc[j] = v;
        m = fmaxf(m, v);
    }
    m = block_max<256>(m);
    float sum = 0.f;
    #pragma unroll
    for (int j = 0; j < 8; j++) {
        int i = tid + j * 256;
        float e = (i < n) ? __expf(loc[j] - m) : 0.f;
        loc[j] = e;
        sum += e;
    }
    sum = block_sum<256>(sum);
    float rinv = 1.f / sum;
    #pragma unroll
    for (int j = 0; j < 8; j++) {
        int i = tid + j * 256;
        if (i < lim) p[i] = loc[j] * rinv;   // zeros above diag within block
    }
}

// ---------------- launch ----------------
extern "C" void kernel_launch(void* const* d_in, const int* in_sizes, int n_in,
                              void* d_out, int out_size)
{
    const int*   positions = (const int*)  d_in[0];
    const float* hidden    = (const float*)d_in[1];
    const float* ln_w      = (const float*)d_in[2];
    const float* w_qkv     = (const float*)d_in[3];
    const float* w_o       = (const float*)d_in[4];
    const float* q_norm_w  = (const float*)d_in[5];
    const float* k_norm_w  = (const float*)d_in[6];
    float*       out       = (float*)d_out;

    // opt in to >48KB dynamic smem (idempotent; not a stream op)
    cudaFuncSetAttribute(k_tc_qkv,    cudaFuncAttributeMaxDynamicSharedMemorySize, GEMM_DSMEM);
    cudaFuncSetAttribute(k_tc_scores, cudaFuncAttributeMaxDynamicSharedMemorySize, GEMM_DSMEM);
    cudaFuncSetAttribute(k_tc_pv,     cudaFuncAttributeMaxDynamicSharedMemorySize, GEMM_DSMEM);
    cudaFuncSetAttribute(k_tc_oproj,  cudaFuncAttributeMaxDynamicSharedMemorySize, GEMM_DSMEM);

    k_rmsnorm_hidden<<<SEQ, 256>>>(hidden, ln_w);
    k_rope_table<<<(SEQ * (HDIM / 2) + 255) / 256, 256>>>(positions);
    k_tc_qkv<<<dim3(QKVN / 128, SEQ / 128), 256, GEMM_DSMEM>>>(w_qkv);
    k_qknorm_rope<<<SEQ, 256>>>(q_norm_w, k_norm_w);
    k_transpose_v<<<dim3(SEQ / 32, HDIM / 32, NKVH), dim3(32, 8)>>>();
    k_tc_scores<<<dim3(TRI_TILES, NHEAD), 256, GEMM_DSMEM>>>();
    k_softmax<<<dim3(SEQ, NHEAD), 256>>>();
    k_tc_pv<<<(SEQ / 128) * NHEAD, 256, GEMM_DSMEM>>>();
    k_tc_oproj<<<dim3(HIDN / 128, SEQ / 128), 256, GEMM_DSMEM>>>(w_o, out);
}